// round 9
// baseline (speedup 1.0000x reference)
#include <cuda_runtime.h>
#include <cuda_fp16.h>

#define NI 2000      // inner tree nodes
#define NL 10000     // leaves / vocab
#define ND 128       // docs
#define FC 64        // mass feature chunk
#define NMASS_CH 157 // ceil(NL/FC)
#define TR_BLKS 157  // transpose tiles of 64 leaves
#define AG_BLKS 400  // argmax: 10 float4-col blocks x 40 row-chunks
#define AG_CH 50     // rows per argmax chunk
#define AG_RB 10     // load batch (MLP)
#define MP_BLKS (3 * NMASS_CH)   // 471 mass-pair blocks
#define SROWH 68     // half2 row stride per feature-pair
// proj-pair: 64x64 doc tiles, 16-feature chunks
#define PFC 16
#define SROW4 68
#define PP_CH (NI / PFC)          // 125
#define PP_BLKS (3 * PP_CH)       // 375

__device__ unsigned long long g_amax[NL];
__device__ float g_massT[NL * ND];    // [leaf][doc]
__device__ float g_projT[NI * ND];    // [node][doc], subtree sums
__device__ float g_top[6 * ND];       // depth<2 terminal accumulators
__device__ float g_S[ND];

__device__ __forceinline__ __half2 u2h2(unsigned u) {
    return *reinterpret_cast<__half2*>(&u);
}
__device__ __forceinline__ unsigned long long pack_key(float v, int idx) {
    unsigned u = __float_as_uint(v);
    u = (u & 0x80000000u) ? ~u : (u | 0x80000000u);
    return ((unsigned long long)u << 32) | (unsigned)idx;
}
__device__ __forceinline__ void red4(float* p, float4 v) {
    asm volatile("red.global.add.v4.f32 [%0], {%1,%2,%3,%4};"
                 :: "l"(p), "f"(v.x), "f"(v.y), "f"(v.z), "f"(v.w) : "memory");
}

// ---------------------------------------------------------------- init
__global__ void k_init(float* __restrict__ out) {
    int i = blockIdx.x * blockDim.x + threadIdx.x;
    if (i < NI * ND) g_projT[i] = 0.0f;
    if (i < 6 * ND) g_top[i] = 0.0f;
    if (i < NL) g_amax[i] = 0ull;
    if (i < ND * ND) out[i] = 0.0f;
    if (i < ND) g_S[i] = 0.0f;
}

// ---------------------------------------------------------------- fused: transpose || argmax || fp16 mass-pair
__global__ void __launch_bounds__(256)
k_fused1(const float* __restrict__ mass, const float* __restrict__ param,
         float* __restrict__ out) {
    __shared__ union {
        float tr[64][132];
        __half2 mp[2][32 * SROWH];
    } sm;
    int tid = threadIdx.x;

    if (blockIdx.x < TR_BLKS) {
        // ---- tiled transpose: mass[d][leaf] -> massT[leaf][d], 64-leaf tiles ----
        int base = blockIdx.x * 64;
        #pragma unroll
        for (int k = 0; k < 8; k++) {
            int idx = tid + k * 256;          // 0..2047
            int doc = idx & 127;
            int l4 = idx >> 7;                // 0..15 (group of 4 leaves)
            if (base + 4 * l4 < NL) {
                float4 v = *(const float4*)&mass[(size_t)doc * NL + base + 4 * l4];
                sm.tr[4 * l4 + 0][doc] = v.x;
                sm.tr[4 * l4 + 1][doc] = v.y;
                sm.tr[4 * l4 + 2][doc] = v.z;
                sm.tr[4 * l4 + 3][doc] = v.w;
            }
        }
        __syncthreads();
        #pragma unroll
        for (int k = 0; k < 8; k++) {
            int idx = tid + k * 256;          // 0..2047
            int d4 = idx & 31;
            int l = idx >> 5;                 // 0..63
            if (base + l < NL) {
                float4 v = *(const float4*)&sm.tr[l][4 * d4];
                *(float4*)&g_massT[(size_t)(base + l) * ND + 4 * d4] = v;
            }
        }
    } else if (blockIdx.x < TR_BLKS + AG_BLKS) {
        // ---- column argmax of param: float4 + explicit 10-deep load batches ----
        int bid = blockIdx.x - TR_BLKS;
        int j4 = (bid % 10) * 256 + tid;      // float4 column
        if (j4 >= NL / 4) return;
        int r0 = (bid / 10) * AG_CH;
        const float4* p = (const float4*)param + (size_t)r0 * (NL / 4) + j4;
        float4 bv = make_float4(-3.4e38f, -3.4e38f, -3.4e38f, -3.4e38f);
        int ix = r0, iy = r0, iz = r0, iw = r0;
        for (int rb = 0; rb < AG_CH; rb += AG_RB) {
            float4 v[AG_RB];
            #pragma unroll
            for (int k = 0; k < AG_RB; k++)
                v[k] = p[(size_t)(rb + k) * (NL / 4)];
            #pragma unroll
            for (int k = 0; k < AG_RB; k++) {
                int r = r0 + rb + k;
                if (v[k].x > bv.x) { bv.x = v[k].x; ix = r; }
                if (v[k].y > bv.y) { bv.y = v[k].y; iy = r; }
                if (v[k].z > bv.z) { bv.z = v[k].z; iz = r; }
                if (v[k].w > bv.w) { bv.w = v[k].w; iw = r; }
            }
        }
        int j = 4 * j4;
        atomicMax(&g_amax[j + 0], pack_key(bv.x, ix));
        atomicMax(&g_amax[j + 1], pack_key(bv.y, iy));
        atomicMax(&g_amax[j + 2], pack_key(bv.z, iz));
        atomicMax(&g_amax[j + 3], pack_key(bv.w, iw));
    } else {
        // ---- fp16 mass-pair: one 64-feature chunk, one 64x64 tile-pair ----
        int pid = blockIdx.x - TR_BLKS - AG_BLKS;
        int tp = pid % 3;                 // 0:(0,0) 1:(0,1)+mirror 2:(1,1)
        int chunk = pid / 3;
        int fb = chunk * FC;
        int nh = min(FC, NL - fb) >> 1;
        int it = (tp == 2) ? 1 : 0;
        int jt = (tp == 0) ? 0 : 1;
        __half2* sa2 = sm.mp[0];
        __half2* sb2 = sm.mp[1];

        const __half2 hz = __float2half2_rn(0.0f);
        #pragma unroll
        for (int k = 0; k < 8; k++) {
            int idx = tid + k * 256;          // 0..2047
            int f2 = idx & 31;
            int row = idx >> 5;               // 0..63
            __half2 ha = hz, hb = hz;
            if (f2 < nh) {
                float2 va = *(const float2*)&mass[(size_t)(it * 64 + row) * NL + fb + 2 * f2];
                float2 vb = *(const float2*)&mass[(size_t)(jt * 64 + row) * NL + fb + 2 * f2];
                ha = __floats2half2_rn(va.x, va.y);
                hb = __floats2half2_rn(vb.x, vb.y);
            }
            sa2[f2 * SROWH + row] = ha;
            sb2[f2 * SROWH + row] = hb;
        }
        __syncthreads();

        int tx = tid & 15, ty = tid >> 4;
        __half2 acc[4][4];
        #pragma unroll
        for (int r = 0; r < 4; r++)
            #pragma unroll
            for (int c = 0; c < 4; c++) acc[r][c] = hz;

        #pragma unroll 4
        for (int f2 = 0; f2 < 32; f2++) {
            uint4 ua = *(const uint4*)&sa2[f2 * SROWH + ty * 4];
            uint4 ub = *(const uint4*)&sb2[f2 * SROWH + tx * 4];
            __half2 ar[4] = {u2h2(ua.x), u2h2(ua.y), u2h2(ua.z), u2h2(ua.w)};
            __half2 br[4] = {u2h2(ub.x), u2h2(ub.y), u2h2(ub.z), u2h2(ub.w)};
            #pragma unroll
            for (int r = 0; r < 4; r++)
                #pragma unroll
                for (int c = 0; c < 4; c++)
                    acc[r][c] = __hadd2(acc[r][c], __hmin2(ar[r], br[c]));
        }

        int ib = it * 64 + ty * 4, jb = jt * 64 + tx * 4;
        #pragma unroll
        for (int r = 0; r < 4; r++)
            #pragma unroll
            for (int c = 0; c < 4; c++) {
                float2 f = __half22float2(acc[r][c]);
                float v = -2.0f * (f.x + f.y);
                atomicAdd(&out[(ib + r) * ND + (jb + c)], v);
                if (tp == 1)
                    atomicAdd(&out[(jb + c) * ND + (ib + r)], v);
            }
    }
}

// ---------------------------------------------------------------- scatter: per leaf, v4-REDG mass row into ancestors (depth>=2)
// chain terminates into g_top[n] (n<6), which therefore accumulates the FULL
// subtree sum of node n (every descendant chain ends there).
__global__ void __launch_bounds__(256)
k_scatter() {
    int w = (blockIdx.x * 8 + (threadIdx.x >> 5)) * 2;  // first leaf of pair
    int lane = threadIdx.x & 31;
    #pragma unroll
    for (int u = 0; u < 2; u++) {
        int j = w + u;
        if (j >= NL) return;
        float4 v = *(const float4*)&g_massT[(size_t)j * ND + lane * 4];
        int n = (int)(unsigned)(g_amax[j] & 0xFFFFFFFFull);
        while (n >= 6) {
            red4(&g_projT[(size_t)n * ND + lane * 4], v);
            n = (n - 1) / 5;
        }
        red4(&g_top[n * ND + lane * 4], v);
    }
}

// ---------------------------------------------------------------- finish nodes 0..5 + S[d]
// g_top[p] (p=1..5) IS the subtree sum of p (no child re-add!).
// proj[0] = g_top[0] + sum_{p=1..5} g_top[p].
__global__ void __launch_bounds__(128)
k_top() {
    int d = threadIdx.x;       // 0..127
    int b = blockIdx.x;        // 0..15, rows [125b, 125b+125)
    float part = 0.0f;
    if (b == 0) {
        float tot = 0.0f;
        #pragma unroll
        for (int p = 1; p <= 5; p++) {
            float s = g_top[p * ND + d];
            g_projT[(size_t)p * ND + d] = s;
            tot += s;
        }
        float r0 = g_top[d] + tot;
        g_projT[d] = r0;
        part = r0 + tot;
        #pragma unroll 4
        for (int row = 6; row < 125; row++)
            part += g_projT[(size_t)row * ND + d];
        part += 1.0f;   // sum(mass) == 1 per doc
    } else {
        #pragma unroll 4
        for (int row = b * 125; row < b * 125 + 125; row++)
            part += g_projT[(size_t)row * ND + d];
    }
    atomicAdd(&g_S[d], part);
}

// ---------------------------------------------------------------- fp32 proj-pair (64x64 tiles, 16-f chunks) || S epilogue
__global__ void __launch_bounds__(256)
k_projpair(float* __restrict__ out) {
    __shared__ float sa[PFC * SROW4];
    __shared__ float sb[PFC * SROW4];
    if (blockIdx.x < PP_BLKS) {
        int pid = blockIdx.x;
        int tp = pid % 3;                 // 0:(0,0) 1:(0,1)+mirror 2:(1,1)
        int fb = (pid / 3) * PFC;
        int it = (tp == 2) ? 1 : 0;
        int jt = (tp == 0) ? 0 : 1;
        int tid = threadIdx.x;

        {   // projT is feature-major: direct float4 fill
            int f = tid >> 4, r4 = tid & 15;
            *(float4*)&sa[f * SROW4 + r4 * 4] =
                *(const float4*)&g_projT[(size_t)(fb + f) * ND + it * 64 + r4 * 4];
            *(float4*)&sb[f * SROW4 + r4 * 4] =
                *(const float4*)&g_projT[(size_t)(fb + f) * ND + jt * 64 + r4 * 4];
        }
        __syncthreads();

        int tx = tid & 15, ty = tid >> 4;
        float acc[4][4];
        #pragma unroll
        for (int r = 0; r < 4; r++)
            #pragma unroll
            for (int c = 0; c < 4; c++) acc[r][c] = 0.0f;

        #pragma unroll
        for (int f = 0; f < PFC; f++) {
            float4 a = *(const float4*)&sa[f * SROW4 + ty * 4];
            float4 b = *(const float4*)&sb[f * SROW4 + tx * 4];
            float ar[4] = {a.x, a.y, a.z, a.w};
            float br[4] = {b.x, b.y, b.z, b.w};
            #pragma unroll
            for (int r = 0; r < 4; r++)
                #pragma unroll
                for (int c = 0; c < 4; c++)
                    acc[r][c] += fminf(ar[r], br[c]);
        }

        int ib = it * 64 + ty * 4, jb = jt * 64 + tx * 4;
        #pragma unroll
        for (int r = 0; r < 4; r++)
            #pragma unroll
            for (int c = 0; c < 4; c++) {
                float v = -2.0f * acc[r][c];
                atomicAdd(&out[(ib + r) * ND + (jb + c)], v);
                if (tp == 1)
                    atomicAdd(&out[(jb + c) * ND + (ib + r)], v);
            }
    } else {
        int e = (blockIdx.x - PP_BLKS) * 256 + threadIdx.x;  // 0..16383
        atomicAdd(&out[e], g_S[e >> 7] + g_S[e & 127]);
    }
}

// ---------------------------------------------------------------- launch
extern "C" void kernel_launch(void* const* d_in, const int* in_sizes, int n_in,
                              void* d_out, int out_size) {
    const float* mass  = (const float*)d_in[0];   // (128, 10000) f32
    const float* param = (const float*)d_in[1];   // (2000, 10000) f32
    float* out = (float*)d_out;                   // (128, 128) f32

    k_init<<<(NI * ND + 255) / 256, 256>>>(out);
    k_fused1<<<TR_BLKS + AG_BLKS + MP_BLKS, 256>>>(mass, param, out);
    k_scatter<<<(NL + 15) / 16, 256>>>();
    k_top<<<16, 128>>>();
    k_projpair<<<PP_BLKS + (ND * ND) / 256, 256>>>(out);
}

// round 11
// speedup vs baseline: 2.2253x; 2.2253x over previous
#include <cuda_runtime.h>
#include <cuda_fp16.h>

#define NI 2000      // inner tree nodes
#define NL 10000     // leaves / vocab
#define ND 128       // docs
#define PP 2048      // padded proj width
#define FC 64        // mass feature chunk
#define NMASS_CH 157 // ceil(NL/FC)
#define AG_BLKS 400  // argmax: 10 float4-col blocks x 40 row-chunks
#define AG_CH 50     // rows per argmax chunk
#define AG_RB 10     // load batch (MLP)
#define MP1_CH 79    // masspair chunks in fused1 (0..78)
#define MP1_BLKS (3 * MP1_CH)              // 237
#define MP2_BLKS (3 * (NMASS_CH - MP1_CH)) // 234
#define SROWH 68     // half2 row stride per feature-pair
// proj-pair (R4-measured config): 32-doc tiles, 64-f chunks, 2x2 micro
#define PT 32
#define PSROW 36
#define NPP 10
#define PP_BLKS (NPP * (PP / FC))   // 320

__device__ unsigned long long g_amax[NL];
__device__ float g_proj[ND * PP];
__device__ float g_S[ND];

__constant__ int c_it[NPP] = {0,0,0,0,1,1,1,2,2,3};
__constant__ int c_jt[NPP] = {0,1,2,3,1,2,3,2,3,3};

__device__ __forceinline__ __half2 u2h2(unsigned u) {
    return *reinterpret_cast<__half2*>(&u);
}
__device__ __forceinline__ unsigned long long pack_key(float v, int idx) {
    unsigned u = __float_as_uint(v);
    u = (u & 0x80000000u) ? ~u : (u | 0x80000000u);
    return ((unsigned long long)u << 32) | (unsigned)idx;
}

// ---------------------------------------------------------------- init
__global__ void k_init(float* __restrict__ out) {
    int i = blockIdx.x * blockDim.x + threadIdx.x;
    if (i < NL) g_amax[i] = 0ull;
    if (i < ND * ND) out[i] = 0.0f;
}

// ---------------------------------------------------------------- fp16 mass-pair worker (one 64-f chunk, 64x64 tile-pair)
__device__ __forceinline__ void masspair_block(
    const float* __restrict__ mass, float* __restrict__ out,
    int pid, __half2* sa2, __half2* sb2)
{
    int tp = pid % 3;                 // 0:(0,0) 1:(0,1)+mirror 2:(1,1)
    int chunk = pid / 3;
    int fb = chunk * FC;
    int nh = min(FC, NL - fb) >> 1;   // valid half2 feature-pairs
    int it = (tp == 2) ? 1 : 0;
    int jt = (tp == 0) ? 0 : 1;
    int tid = threadIdx.x;

    const __half2 hz = __float2half2_rn(0.0f);
    #pragma unroll
    for (int k = 0; k < 8; k++) {
        int idx = tid + k * 256;          // 0..2047
        int f2 = idx & 31;
        int row = idx >> 5;               // 0..63
        __half2 ha = hz, hb = hz;
        if (f2 < nh) {
            float2 va = *(const float2*)&mass[(size_t)(it * 64 + row) * NL + fb + 2 * f2];
            float2 vb = *(const float2*)&mass[(size_t)(jt * 64 + row) * NL + fb + 2 * f2];
            ha = __floats2half2_rn(va.x, va.y);
            hb = __floats2half2_rn(vb.x, vb.y);
        }
        sa2[f2 * SROWH + row] = ha;
        sb2[f2 * SROWH + row] = hb;
    }
    __syncthreads();

    int tx = tid & 15, ty = tid >> 4;
    __half2 acc[4][4];
    #pragma unroll
    for (int r = 0; r < 4; r++)
        #pragma unroll
        for (int c = 0; c < 4; c++) acc[r][c] = hz;

    #pragma unroll 4
    for (int f2 = 0; f2 < 32; f2++) {
        uint4 ua = *(const uint4*)&sa2[f2 * SROWH + ty * 4];
        uint4 ub = *(const uint4*)&sb2[f2 * SROWH + tx * 4];
        __half2 ar[4] = {u2h2(ua.x), u2h2(ua.y), u2h2(ua.z), u2h2(ua.w)};
        __half2 br[4] = {u2h2(ub.x), u2h2(ub.y), u2h2(ub.z), u2h2(ub.w)};
        #pragma unroll
        for (int r = 0; r < 4; r++)
            #pragma unroll
            for (int c = 0; c < 4; c++)
                acc[r][c] = __hadd2(acc[r][c], __hmin2(ar[r], br[c]));
    }

    int ib = it * 64 + ty * 4, jb = jt * 64 + tx * 4;
    #pragma unroll
    for (int r = 0; r < 4; r++)
        #pragma unroll
        for (int c = 0; c < 4; c++) {
            float2 f = __half22float2(acc[r][c]);
            float v = -2.0f * (f.x + f.y);
            atomicAdd(&out[(ib + r) * ND + (jb + c)], v);
            if (tp == 1)
                atomicAdd(&out[(jb + c) * ND + (ib + r)], v);
        }
}

// ---------------------------------------------------------------- fused1: argmax (batch-10 MLP) || masspair chunks 0..78
__global__ void __launch_bounds__(256)
k_fused1(const float* __restrict__ mass, const float* __restrict__ param,
         float* __restrict__ out) {
    __shared__ __half2 smp[2][32 * SROWH];
    if (blockIdx.x < AG_BLKS) {
        int bid = blockIdx.x;
        int j4 = (bid % 10) * 256 + threadIdx.x;    // float4 column
        if (j4 >= NL / 4) return;
        int r0 = (bid / 10) * AG_CH;
        const float4* p = (const float4*)param + (size_t)r0 * (NL / 4) + j4;
        float4 bv = make_float4(-3.4e38f, -3.4e38f, -3.4e38f, -3.4e38f);
        int ix = r0, iy = r0, iz = r0, iw = r0;
        for (int rb = 0; rb < AG_CH; rb += AG_RB) {
            float4 v[AG_RB];
            #pragma unroll
            for (int k = 0; k < AG_RB; k++)
                v[k] = p[(size_t)(rb + k) * (NL / 4)];
            #pragma unroll
            for (int k = 0; k < AG_RB; k++) {
                int r = r0 + rb + k;
                if (v[k].x > bv.x) { bv.x = v[k].x; ix = r; }
                if (v[k].y > bv.y) { bv.y = v[k].y; iy = r; }
                if (v[k].z > bv.z) { bv.z = v[k].z; iz = r; }
                if (v[k].w > bv.w) { bv.w = v[k].w; iw = r; }
            }
        }
        int j = 4 * j4;
        atomicMax(&g_amax[j + 0], pack_key(bv.x, ix));
        atomicMax(&g_amax[j + 1], pack_key(bv.y, iy));
        atomicMax(&g_amax[j + 2], pack_key(bv.z, iz));
        atomicMax(&g_amax[j + 3], pack_key(bv.w, iw));
    } else {
        masspair_block(mass, out, blockIdx.x - AG_BLKS, smp[0], smp[1]);
    }
}

// ---------------------------------------------------------------- fused2: proj scatter+treesum (128 blocks) || masspair 79..156
__global__ void __launch_bounds__(256)
k_fused2(const float* __restrict__ mass, float* __restrict__ out) {
    __shared__ union {
        struct { float s[NI]; float red[256]; } pj;
        __half2 mp[2][32 * SROWH];
    } sm;
    int tid = threadIdx.x;

    if (blockIdx.x < ND) {
        // ---- proj for doc d: shared scatter + bottom-up tree-sum ----
        int d = blockIdx.x;
        float* s = sm.pj.s;
        for (int i = tid; i < NI; i += 256) s[i] = 0.0f;
        __syncthreads();
        const float4* m4 = (const float4*)(mass + (size_t)d * NL);
        float msum = 0.0f;
        for (int j4 = tid; j4 < NL / 4; j4 += 256) {
            float4 v = m4[j4];
            msum += v.x + v.y + v.z + v.w;
            int a0 = (int)(unsigned)(__ldg(&g_amax[4 * j4 + 0]) & 0xFFFFFFFFull);
            int a1 = (int)(unsigned)(__ldg(&g_amax[4 * j4 + 1]) & 0xFFFFFFFFull);
            int a2 = (int)(unsigned)(__ldg(&g_amax[4 * j4 + 2]) & 0xFFFFFFFFull);
            int a3 = (int)(unsigned)(__ldg(&g_amax[4 * j4 + 3]) & 0xFFFFFFFFull);
            atomicAdd(&s[a0], v.x);
            atomicAdd(&s[a1], v.y);
            atomicAdd(&s[a2], v.z);
            atomicAdd(&s[a3], v.w);
        }
        __syncthreads();
        // bottom-up: parents {156..399},{31..155},{6..30},{1..5},{0}
        const int lo[5] = {156, 31, 6, 1, 0};
        const int hi[5] = {399, 155, 30, 5, 0};
        for (int L = 0; L < 5; L++) {
            for (int p = lo[L] + tid; p <= hi[L]; p += 256) {
                float acc = s[p];
                int c0 = 5 * p + 1;
                #pragma unroll
                for (int c = 0; c < 5; c++)
                    if (c0 + c < NI) acc += s[c0 + c];
                s[p] = acc;
            }
            __syncthreads();
        }
        float psum = 0.0f;
        for (int i = tid; i < NI; i += 256) psum += s[i];
        sm.pj.red[tid] = msum + psum;
        __syncthreads();
        for (int w = 128; w > 0; w >>= 1) {
            if (tid < w) sm.pj.red[tid] += sm.pj.red[tid + w];
            __syncthreads();
        }
        if (tid == 0) g_S[d] = sm.pj.red[0];
        float* gp = g_proj + (size_t)d * PP;
        for (int i = tid; i < PP; i += 256)
            gp[i] = (i < NI) ? s[i] : 0.0f;
    } else {
        int pid = (blockIdx.x - ND) + 3 * MP1_CH;   // chunks 79..156
        masspair_block(mass, out, pid, sm.mp[0], sm.mp[1]);
    }
}

// ---------------------------------------------------------------- fp32 proj-pair (R4 config: 32-tiles, 64-f chunks, 2x2) || S epilogue
__global__ void __launch_bounds__(256)
k_projpair(float* __restrict__ out) {
    __shared__ float sa[FC * PSROW];
    __shared__ float sb[FC * PSROW];
    if (blockIdx.x < PP_BLKS) {
        int pid = blockIdx.x;
        int tp = pid % NPP;
        int fb = (pid / NPP) * FC;
        int it = c_it[tp], jt = c_jt[tp];
        int tid = threadIdx.x;

        #pragma unroll
        for (int k = 0; k < 8; k++) {
            int idx = tid + k * 256;          // 0..2047 = 64 f x 32 rows
            int f = idx & 63;
            int row = idx >> 6;               // 0..31
            sa[f * PSROW + row] = g_proj[(size_t)(it * PT + row) * PP + fb + f];
            sb[f * PSROW + row] = g_proj[(size_t)(jt * PT + row) * PP + fb + f];
        }
        __syncthreads();

        int tx = tid & 15, ty = tid >> 4;
        float acc[2][2] = {{0.f, 0.f}, {0.f, 0.f}};
        #pragma unroll 8
        for (int f = 0; f < FC; f++) {
            float2 a = *(const float2*)&sa[f * PSROW + ty * 2];
            float2 b = *(const float2*)&sb[f * PSROW + tx * 2];
            acc[0][0] += fminf(a.x, b.x);
            acc[0][1] += fminf(a.x, b.y);
            acc[1][0] += fminf(a.y, b.x);
            acc[1][1] += fminf(a.y, b.y);
        }

        int ib = it * PT + ty * 2, jb = jt * PT + tx * 2;
        #pragma unroll
        for (int r = 0; r < 2; r++)
            #pragma unroll
            for (int c = 0; c < 2; c++) {
                float v = -2.0f * acc[r][c];
                atomicAdd(&out[(ib + r) * ND + (jb + c)], v);
                if (it != jt)
                    atomicAdd(&out[(jb + c) * ND + (ib + r)], v);
            }
    } else {
        int e = (blockIdx.x - PP_BLKS) * 256 + threadIdx.x;  // 0..16383
        atomicAdd(&out[e], g_S[e >> 7] + g_S[e & 127]);
    }
}

// ---------------------------------------------------------------- launch
extern "C" void kernel_launch(void* const* d_in, const int* in_sizes, int n_in,
                              void* d_out, int out_size) {
    const float* mass  = (const float*)d_in[0];   // (128, 10000) f32
    const float* param = (const float*)d_in[1];   // (2000, 10000) f32
    float* out = (float*)d_out;                   // (128, 128) f32

    k_init<<<64, 256>>>(out);
    k_fused1<<<AG_BLKS + MP1_BLKS, 256>>>(mass, param, out);
    k_fused2<<<ND + MP2_BLKS, 256>>>(mass, out);
    k_projpair<<<PP_BLKS + (ND * ND) / 256, 256>>>(out);
}